// round 8
// baseline (speedup 1.0000x reference)
#include <cuda_runtime.h>
#include <cstdint>
#include <cstddef>

#define MPROP 36
#define NS    10
#define TPB   256
#define BPB   64          // batches per block (8 per warp, 4 threads per batch)

#define NEG_INF __int_as_float(0xff800000)

// Fused piecewise-linear eval: tab[i] = (cs[min(i,16)], nw[min(i+1,16)])
__device__ __forceinline__ float pwl1(const float2* __restrict__ t, float x) {
    float xd = x * 16.0f;
    int ip = (int)xd;                 // x >= 0 everywhere -> trunc == floor
    float frac = xd - (float)ip;
    float2 e = t[min(ip, 16)];
    return __fmaf_rn(frac, e.y, e.x);
}

__global__ __launch_bounds__(TPB)
void count_kernel(const float* __restrict__ boxes,      // [B,4,36]
                  const float* __restrict__ attention,  // [B,36]
                  const float* __restrict__ fw,         // [8,17]
                  float* __restrict__ out,              // [B,11]
                  int B)
{
    __shared__ float2 s_tab[8][17];

    const int tid = threadIdx.x;

    // ---- build fused PWL tables (8 threads, one function each) ----
    if (tid < 8) {
        float aw[17];
        float s = 0.0f;
        #pragma unroll
        for (int k = 0; k < 17; k++) { aw[k] = fabsf(fw[tid * 17 + k]); s += aw[k]; }
        float nw[17], cs[17];
        #pragma unroll
        for (int k = 0; k < 17; k++) nw[k] = aw[k] / s;
        cs[0] = nw[0];
        #pragma unroll
        for (int k = 1; k < 17; k++) cs[k] = cs[k - 1] + nw[k];
        #pragma unroll
        for (int i = 0; i < 17; i++)
            s_tab[tid][i] = make_float2(cs[i], nw[min(i + 1, 16)]);
    }
    __syncthreads();

    const int lane = tid & 31;
    const int warp = tid >> 5;
    const int t    = lane >> 3;          // role within quad: 0..3
    const int bl   = lane & 7;           // batch slot within warp
    const int b    = blockIdx.x * BPB + warp * 8 + bl;
    const bool act = (b < B);

    // ---- load this thread's 9 attention values (quad covers 36) ----
    const int base = t * 9;              // global index base of local chunk
    float v[9];
    #pragma unroll
    for (int k = 0; k < 9; k++) v[k] = NEG_INF;
    if (act) {
        const float* arow = attention + (size_t)b * MPROP + base;
        #pragma unroll
        for (int k = 0; k < 9; k++) v[k] = arow[k];
    }

    // ---- top-10 of 36: register tournament + quad shfl argmax ----
    float osat[3] = {0.0f, 0.0f, 0.0f};
    int   osix[3] = {0, 0, 0};
    #pragma unroll
    for (int r = 0; r < NS; r++) {
        // local argmax over v[0..8], left-biased ties (lowest index wins)
        float mv; int mi;
        {
            float a0 = v[0]; int i0_ = 0; if (v[1] > a0) { a0 = v[1]; i0_ = 1; }
            float a2 = v[2]; int i2_ = 2; if (v[3] > a2) { a2 = v[3]; i2_ = 3; }
            float a4 = v[4]; int i4_ = 4; if (v[5] > a4) { a4 = v[5]; i4_ = 5; }
            float a6 = v[6]; int i6_ = 6; if (v[7] > a6) { a6 = v[7]; i6_ = 7; }
            if (a2 > a0) { a0 = a2; i0_ = i2_; }
            if (a6 > a4) { a4 = a6; i4_ = i6_; }
            if (a4 > a0) { a0 = a4; i0_ = i4_; }
            if (v[8] > a0) { a0 = v[8]; i0_ = 8; }
            mv = a0; mi = i0_;
        }
        float bval = mv;
        int   bidx = base + mi;          // global index 0..35
        // quad argmax (lanes differing in bits 3,4 share a batch)
        #pragma unroll
        for (int off = 8; off < 32; off <<= 1) {
            float ov = __shfl_xor_sync(0xffffffffu, bval, off);
            int   oi = __shfl_xor_sync(0xffffffffu, bidx, off);
            bool take = (ov > bval) || (ov == bval && oi < bidx);
            bval = take ? ov : bval;
            bidx = take ? oi : bidx;
        }
        // knockout winner if it lives in this thread's chunk
        int d = bidx - base;
        #pragma unroll
        for (int k = 0; k < 9; k++)
            if (d == k) v[k] = NEG_INF;
        // capture if this thread owns selection slot r (ownership: r & 3 == t)
        if ((r & 3) == t) { osat[r >> 2] = bval; osix[r >> 2] = bidx; }
    }

    // ---- load boxes for owned selections (r = 4k + t), area + sigmoid ----
    float oy1[3], ox1[3], oy2[3], ox2[3], oar[3], oas[3], orr[3];
    const float* bb = boxes + (size_t)b * (4 * MPROP);
    #pragma unroll
    for (int k = 0; k < 3; k++) {
        const bool valid = act && (4 * k + t < NS);
        float yy1 = 0.0f, xx1 = 0.0f, yy2 = 0.0f, xx2 = 0.0f, sv = 0.0f;
        if (valid) {
            int ii = osix[k];
            yy1 = bb[ii];
            xx1 = bb[MPROP + ii];
            yy2 = bb[2 * MPROP + ii];
            xx2 = bb[3 * MPROP + ii];
            sv  = osat[k];
        }
        oy1[k] = yy1; ox1[k] = xx1; oy2[k] = yy2; ox2[k] = xx2;
        oar[k] = fmaxf(yy2 - yy1, 0.0f) * fmaxf(xx2 - xx1, 0.0f);
        oas[k] = __fdividef(1.0f, 1.0f + __expf(-sv));
    }

    const float2* t0 = s_tab[0];
    const float2* t1 = s_tab[1];
    const float2* t2 = s_tab[2];
    const float2* t5 = s_tab[5];
    const float2* t6 = s_tab[6];
    const float2* t7 = s_tab[7];

    // ---- broadcast all 10 sigmoid(att) values to every quad thread ----
    float aj[NS];
    #pragma unroll
    for (int j = 0; j < NS; j++) {
        const int src = ((j & 3) << 3) | bl;   // within-warp source lane
        aj[j] = __shfl_sync(0xffffffffu, oas[j >> 2], src);
    }

    // ---- row sums of similarity: s_i = C * sum_j f2(1-|as_i - as_j|) ----
    const float f2one = s_tab[2][16].x;   // f2(1.0)
    float C2 = f2one * f2one, C4 = C2 * C2, C8 = C4 * C4;
    const float C = C8 * C2;              // f2(1)^10
    #pragma unroll
    for (int k = 0; k < 3; k++) {
        float s = 0.0f;
        #pragma unroll
        for (int j = 0; j < NS; j++)
            s += pwl1(t2, 1.0f - fabsf(oas[k] - aj[j]));
        orr[k] = __fdividef(1.0f, C * s);  // 1 / s_i
    }

    // ---- full 10x10 pass: score + p_d (diagonal handled by general formula) ----
    float scoreT = 0.0f, pdT = 0.0f;
    #pragma unroll
    for (int j = 0; j < NS; j++) {
        const int src = ((j & 3) << 3) | bl;
        float y1j = __shfl_sync(0xffffffffu, oy1[j >> 2], src);
        float x1j = __shfl_sync(0xffffffffu, ox1[j >> 2], src);
        float y2j = __shfl_sync(0xffffffffu, oy2[j >> 2], src);
        float x2j = __shfl_sync(0xffffffffu, ox2[j >> 2], src);
        float arj = __shfl_sync(0xffffffffu, oar[j >> 2], src);
        float rrj = __shfl_sync(0xffffffffu, orr[j >> 2], src);
        float asj = aj[j];
        #pragma unroll
        for (int k = 0; k < 3; k++) {
            float ty = fmaxf(oy1[k], y1j);
            float tx = fmaxf(ox1[k], x1j);
            float by = fminf(oy2[k], y2j);
            float bx = fminf(ox2[k], x2j);
            float inter = fmaxf(by - ty, 0.0f) * fmaxf(bx - tx, 0.0f);
            float uni   = oar[k] + arj - inter + 1e-12f;
            float dm    = 1.0f - __fdividef(inter, uni);   // in [0,1] (fp-safe)
            float f0v = pwl1(t0, oas[k] * asj);
            // f1/f6 share index+frac (same input dm)
            float xd = dm * 16.0f;
            int ip = (int)xd;
            float frac = xd - (float)ip;
            int ii = min(ip, 16);
            float2 e1 = t1[ii];
            float2 e6 = t6[ii];
            float f1v = __fmaf_rn(frac, e1.y, e1.x);
            float f6v = __fmaf_rn(frac, e6.y, e6.x);
            float contrib = (f0v * f1v) * (orr[k] * rrj);
            float pdc = fabsf(f6v - 0.5f);
            const bool valid = (4 * k + t) < NS;   // k<2 always true
            scoreT += valid ? contrib : 0.0f;
            pdT    += valid ? pdc     : 0.0f;
        }
    }

    // ---- corr (diagonal-only) + p_a over owned selections ----
    float corrT = 0.0f, paT = 0.0f;
    #pragma unroll
    for (int k = 0; k < 3; k++) {
        const bool valid = (4 * k + t) < NS;
        float f0d = pwl1(t0, oas[k] * oas[k]);
        float f5d = pwl1(t5, oas[k]);
        corrT += valid ? f0d * orr[k]        : 0.0f;
        paT   += valid ? fabsf(f5d - 0.5f)   : 0.0f;
    }

    // ---- quad reductions (lanes xor 8, 16 share a batch) ----
    #pragma unroll
    for (int off = 8; off < 32; off <<= 1) {
        scoreT += __shfl_xor_sync(0xffffffffu, scoreT, off);
        pdT    += __shfl_xor_sync(0xffffffffu, pdT,    off);
        corrT  += __shfl_xor_sync(0xffffffffu, corrT,  off);
        paT    += __shfl_xor_sync(0xffffffffu, paT,    off);
    }

    // ---- finals (all quad threads compute identically) ----
    float gate = pwl1(t7, paT * 0.1f + pdT * 0.01f);
    float modE = scoreT + corrT;
    float c  = sqrtf(modE + 1e-20f);
    float cc = fminf(c, 10.0f);
    int   ipc = (int)cc;
    float fr  = cc - (float)ipc;
    int i0 = min(ipc, NS);
    int i1 = min(ipc + 1, NS);

    // ---- output: thread t writes k = t, t+4, t+8 ----
    if (act) {
        float* ob = out + (size_t)b * (NS + 1);
        #pragma unroll
        for (int m = 0; m < 3; m++) {
            int k = t + 4 * m;
            if (k < NS + 1) {
                float vv = ((k == i0) ? (1.0f - fr) : 0.0f) + ((k == i1) ? fr : 0.0f);
                ob[k] = gate * vv;
            }
        }
    }
}

extern "C" void kernel_launch(void* const* d_in, const int* in_sizes, int n_in,
                              void* d_out, int out_size) {
    const float* boxes     = (const float*)d_in[0];
    const float* attention = (const float*)d_in[1];
    const float* fw        = (const float*)d_in[2];
    float* out             = (float*)d_out;
    (void)n_in; (void)out_size;
    int B = in_sizes[1] / MPROP;
    int grid = (B + BPB - 1) / BPB;
    count_kernel<<<grid, TPB>>>(boxes, attention, fw, out, B);
}